// round 12
// baseline (speedup 1.0000x reference)
#include <cuda_runtime.h>
#include <cuda_bf16.h>
#include <math.h>
#include <stdint.h>

#define BB 8
#define NN 2048
#define FF 64

typedef unsigned long long u64;
typedef unsigned int u32;

// -------------------- device scratch --------------------
__device__ __align__(16) float2 g_eA[BB * NN];   // (exp(f1), exp(0.2 f1))
__device__ __align__(16) float2 g_eB[BB * NN];   // (exp(f2), exp(0.2 f2))
__device__ __align__(16) u32 g_hTh[BB * FF * (NN / 2)];
__device__ __align__(16) u32 g_hTl[BB * FF * (NN / 2)];
// word g, component c, bit L  <->  adj[g*128 + 4L + c]
__device__ __align__(16) uint4 g_mask[BB * NN * 16];

// -------------------- PTX helpers --------------------
#define FMA2(d, a, b, c) \
    asm("fma.rn.f32x2 %0,%1,%2,%3;" : "=l"(d) : "l"(a), "l"(b), "l"(c))
#define UNPACK2(lo, hi, s) \
    asm("mov.b64 {%0,%1},%2;" : "=f"(lo), "=f"(hi) : "l"(s))

__device__ __forceinline__ float ex2(float x) {
    float r; asm("ex2.approx.ftz.f32 %0,%1;" : "=f"(r) : "f"(x)); return r;
}
__device__ __forceinline__ u32 smem_u32(const void* p) {
    u32 a;
    asm("{.reg .u64 t; cvta.to.shared.u64 t, %1; cvt.u32.u64 %0, t;}"
        : "=r"(a) : "l"(p));
    return a;
}

#define CPASYNC16(saddr, gptr) \
    asm volatile("cp.async.ca.shared.global [%0], [%1], 16;" \
                 :: "r"(saddr), "l"(gptr) : "memory")
#define CPCOMMIT() asm volatile("cp.async.commit_group;" ::: "memory")
#define CPWAIT0()  asm volatile("cp.async.wait_group 0;" ::: "memory")
#define CPWAIT1()  asm volatile("cp.async.wait_group 1;" ::: "memory")

#define LDSM4(r0, r1, r2, r3, addr) \
    asm volatile("ldmatrix.sync.aligned.m8n8.x4.shared.b16 {%0,%1,%2,%3}, [%4];" \
                 : "=r"(r0), "=r"(r1), "=r"(r2), "=r"(r3) : "r"(addr))

#define MMA16816(d, a, b0, b1) \
    asm volatile("mma.sync.aligned.m16n8k16.row.col.f32.bf16.bf16.f32 " \
                 "{%0,%1,%2,%3}, {%4,%5,%6,%7}, {%8,%9}, {%0,%1,%2,%3};" \
                 : "+f"((d)[0]), "+f"((d)[1]), "+f"((d)[2]), "+f"((d)[3]) \
                 : "r"((a)[0]), "r"((a)[1]), "r"((a)[2]), "r"((a)[3]), \
                   "r"(b0), "r"(b1))

__device__ __forceinline__ void split2(float a, float b, u32& hi, u32& lo) {
    asm("cvt.rn.bf16x2.f32 %0,%1,%2;" : "=r"(hi) : "f"(b), "f"(a));
    float ra = a - __uint_as_float(hi << 16);
    float rb = b - __uint_as_float(hi & 0xFFFF0000u);
    asm("cvt.rn.bf16x2.f32 %0,%1,%2;" : "=r"(lo) : "f"(rb), "f"(ra));
}

// ---------------------------------------------------------------------------
// Kernel 1 (validated R10): h = inp@W, per-node exp factors, H^T bf16 planes;
// blocks [128,384): adj -> ballot bitmask.
// ---------------------------------------------------------------------------
#define PR2 130
#define KHF_SMEM (FF * FF * 4 + FF * PR2 * 8)

__global__ void __launch_bounds__(512) k_hf(const float* __restrict__ inp,
                                            const float* __restrict__ W,
                                            const float* __restrict__ a,
                                            const int* __restrict__ adj) {
    const int t = threadIdx.x;
    const float L2E = 1.44269504089f;

    if (blockIdx.x >= 128) {
        const int gw = (blockIdx.x - 128) * 16 + (t >> 5);
        const int lane = t & 31;
        const int4* src = (const int4*)adj + (size_t)gw * 64 * 32 + lane;
        uint4* dst = g_mask + (size_t)gw * 64;
#pragma unroll 1
        for (int r = 0; r < 8; ++r) {
            int4 v[8];
#pragma unroll
            for (int s = 0; s < 8; ++s) v[s] = src[(r * 8 + s) * 32];
#pragma unroll
            for (int s = 0; s < 8; ++s) {
                uint4 m;
                m.x = __ballot_sync(0xffffffffu, v[s].x > 0);
                m.y = __ballot_sync(0xffffffffu, v[s].y > 0);
                m.z = __ballot_sync(0xffffffffu, v[s].z > 0);
                m.w = __ballot_sync(0xffffffffu, v[s].w > 0);
                if (lane == 0) dst[r * 8 + s] = m;
            }
        }
        return;
    }

    extern __shared__ char smem[];
    float*  Ws   = (float*)smem;
    float2* IsT2 = (float2*)(smem + FF * FF * 4);

    const int row0 = blockIdx.x * 128;
    const int tx   = t & 7;
    const int ty   = t >> 3;

    ((float4*)Ws)[t]       = ((const float4*)W)[t];
    ((float4*)Ws)[t + 512] = ((const float4*)W)[t + 512];
#pragma unroll
    for (int q = 0; q < 4; ++q) {
        int idx = t + 512 * q;
        int r = idx >> 4, k4 = (idx & 15) * 4;
        float4 v = ((const float4*)(inp + (size_t)(row0 + r) * FF))[idx & 15];
        IsT2[(k4 + 0) * PR2 + r] = make_float2(v.x, v.x);
        IsT2[(k4 + 1) * PR2 + r] = make_float2(v.y, v.y);
        IsT2[(k4 + 2) * PR2 + r] = make_float2(v.z, v.z);
        IsT2[(k4 + 3) * PR2 + r] = make_float2(v.w, v.w);
    }
    __syncthreads();

    u64 acc[2][4] = {};
#pragma unroll 8
    for (int k = 0; k < FF; ++k) {
        ulonglong2 pp = *(const ulonglong2*)&IsT2[k * PR2 + ty * 2];
        u64 pd[2] = {pp.x, pp.y};
        ulonglong2 h0 = *(const ulonglong2*)&Ws[k * FF + tx * 8];
        ulonglong2 h1 = *(const ulonglong2*)&Ws[k * FF + tx * 8 + 4];
        u64 hp[4] = {h0.x, h0.y, h1.x, h1.y};
#pragma unroll
        for (int r = 0; r < 2; ++r)
#pragma unroll
            for (int c = 0; c < 4; ++c) FMA2(acc[r][c], pd[r], hp[c], acc[r][c]);
    }

    float hv[2][8];
#pragma unroll
    for (int r = 0; r < 2; ++r)
#pragma unroll
        for (int c = 0; c < 4; ++c)
            UNPACK2(hv[r][2 * c], hv[r][2 * c + 1], acc[r][c]);

    float av1[8], av2[8];
#pragma unroll
    for (int c = 0; c < 8; ++c) {
        av1[c] = __ldg(a + tx * 8 + c);
        av2[c] = __ldg(a + 64 + tx * 8 + c);
    }
#pragma unroll
    for (int r = 0; r < 2; ++r) {
        float s1 = 0.f, s2 = 0.f;
#pragma unroll
        for (int c = 0; c < 8; ++c) { s1 += hv[r][c] * av1[c]; s2 += hv[r][c] * av2[c]; }
#pragma unroll
        for (int o = 1; o < 8; o <<= 1) {
            s1 += __shfl_xor_sync(0xffffffffu, s1, o);
            s2 += __shfl_xor_sync(0xffffffffu, s2, o);
        }
        if (tx == 0) {
            const int row = row0 + ty * 2 + r;
            g_eA[row] = make_float2(ex2(s1 * L2E), ex2(0.2f * s1 * L2E));
            g_eB[row] = make_float2(ex2(s2 * L2E), ex2(0.2f * s2 * L2E));
        }
    }

    __syncthreads();
    u32* trH = (u32*)(smem + 16384);
    u32* trL = trH + 64 * 68;
#pragma unroll
    for (int c = 0; c < 8; ++c) {
        const int n = tx * 8 + c;
        u32 hi, lo;
        split2(hv[0][c], hv[1][c], hi, lo);
        trH[n * 68 + ty] = hi;
        trL[n * 68 + ty] = lo;
    }
    __syncthreads();

    const int b     = row0 >> 11;
    const int jloc0 = row0 & 2047;
    float4* dH = (float4*)g_hTh;
    float4* dL = (float4*)g_hTl;
#pragma unroll
    for (int u = 0; u < 2; ++u) {
        const int idx = t + 512 * u;
        const int n = idx >> 4, c = idx & 15;
        const int gidx = (b * 64 + n) * 256 + (jloc0 >> 3) + c;
        dH[gidx] = *(const float4*)(trH + n * 68 + c * 4);
        dL[gidx] = *(const float4*)(trL + n * 68 + c * 4);
    }
}

// ---------------------------------------------------------------------------
// Kernel 2: P computed directly in MMA A-fragment registers (no P smem).
// 256 CTAs x 256 threads, 2 CTAs/SM. Warp = (m-block w&3) x (k-half w>>2).
// Mask consumption matches the interleaved ballot layout:
//   tile-local j = kh*64 + kk*16 + 2*tig + {0,1,8,9}
//   component = (2*tig)&3 -> (x|z for even j, y|w for odd j, z/w when tig odd)
//   bit = j>>2 = kh*16 + kk*4 + (tig>>1)  (+2 for the +8 elements)
// ---------------------------------------------------------------------------
#define PSTRIDE 272
#define HT_STG  34816            // per stage: HTH(0), HTL(17408)
#define OF_HTL  17408
#define SM_MSK  69632
#define SM_EB   86016
#define SM_SP   102400
#define ATTN_SMEM 102912

__global__ void __launch_bounds__(256, 2) k_attn(float* __restrict__ out) {
    extern __shared__ char smem[];
    const u32 sb = smem_u32(smem);
    const int t = threadIdx.x;
    const int w = t >> 5, lane = t & 31;
    const int i0 = blockIdx.x * 64;
    const int b  = blockIdx.y;
    const int mq = w & 3;            // m16 block
    const int kh = w >> 2;           // k-half (0: k0-63, 1: k64-127)

    uint4*  msk_s = (uint4*)(smem + SM_MSK);
    float4* ebs4  = (float4*)(smem + SM_EB);

    const float4* hsH = (const float4*)g_hTh + (size_t)b * 64 * 256;
    const float4* hsL = (const float4*)g_hTl + (size_t)b * 64 * 256;
    const int stg_n = t >> 4, stg_c = t & 15;

    // ---- prologue: masks + eB pairs + HT(0) ----
    {
        const uint4* gm = g_mask + (size_t)(b * NN + i0) * 16;
#pragma unroll
        for (int u = 0; u < 4; ++u) msk_s[t + 256 * u] = gm[t + 256 * u];
        const float4* ebg = (const float4*)(g_eB + (size_t)b * NN);
#pragma unroll
        for (int u = 0; u < 4; ++u) ebs4[t + 256 * u] = ebg[t + 256 * u];
#pragma unroll
        for (int u = 0; u < 4; ++u) {
            const int n = stg_n + 16 * u;
            const int g = (n << 8) + stg_c;
            const u32 so = (u32)(n * PSTRIDE + stg_c * 16);
            CPASYNC16(sb + so, hsH + g);
            CPASYNC16(sb + OF_HTL + so, hsL + g);
        }
        CPCOMMIT();
    }

    const int tig  = lane & 3;
    const int rloc = mq * 16 + (lane >> 2);     // CTA-local row of fragment
    const float2 eA0 = __ldg(&g_eA[b * NN + i0 + rloc]);
    const float2 eA1 = __ldg(&g_eA[b * NN + i0 + rloc + 8]);
    float Sacc0 = 0.f, Sacc1 = 0.f;

    const u32 rowsel = (u32)(lane & 15);
    const u32 colsel = (u32)((lane >> 4) * 16);
    const u32 aBbase = sb + rowsel * PSTRIDE + colsel + (u32)kh * 128;
    const u32 bbase  = (u32)(kh * 16 + (tig >> 1));

    float d[8][4] = {};

    __syncthreads();   // masks/eB visible

    for (int tt = 0; tt < 16; ++tt) {
        const u32 stoff = (u32)((tt & 1) * HT_STG);

        // stage HT(tt+1) into other buffer
        if (tt < 15) {
            const u32 stoffN = (u32)(((tt + 1) & 1) * HT_STG);
#pragma unroll
            for (int u = 0; u < 4; ++u) {
                const int n = stg_n + 16 * u;
                const int g = (n << 8) + ((tt + 1) << 4) + stg_c;
                const u32 so = (u32)(n * PSTRIDE + stg_c * 16);
                CPASYNC16(sb + stoffN + so, hsH + g);
                CPASYNC16(sb + stoffN + OF_HTL + so, hsL + g);
            }
            CPCOMMIT();
        }

        // ---- scores -> A fragments (registers only) ----
        const uint4 mr0 = msk_s[rloc * 16 + tt];
        const uint4 mr1 = msk_s[(rloc + 8) * 16 + tt];
        const u32 We0 = (tig & 1) ? mr0.z : mr0.x;   // even-j elements
        const u32 Wo0 = (tig & 1) ? mr0.w : mr0.y;   // odd-j elements
        const u32 We1 = (tig & 1) ? mr1.z : mr1.x;
        const u32 Wo1 = (tig & 1) ? mr1.w : mr1.y;

        u32 AH[4][4], AL[4][4];
#pragma unroll
        for (int kk = 0; kk < 4; ++kk) {
            const int idx = tt * 64 + kh * 32 + kk * 8 + tig;
            const float4 e0 = ebs4[idx];        // (B,b) for j, j+1
            const float4 e1 = ebs4[idx + 4];    // (B,b) for j+8, j+9
            const u32 b0 = bbase + (u32)(kk * 4);

            float p00 = ((We0 >> b0) & 1u)       ? fmaxf(eA0.x * e0.x, eA0.y * e0.y) : 0.f;
            float p01 = ((Wo0 >> b0) & 1u)       ? fmaxf(eA0.x * e0.z, eA0.y * e0.w) : 0.f;
            float p02 = ((We0 >> (b0 + 2)) & 1u) ? fmaxf(eA0.x * e1.x, eA0.y * e1.y) : 0.f;
            float p03 = ((Wo0 >> (b0 + 2)) & 1u) ? fmaxf(eA0.x * e1.z, eA0.y * e1.w) : 0.f;
            float p10 = ((We1 >> b0) & 1u)       ? fmaxf(eA1.x * e0.x, eA1.y * e0.y) : 0.f;
            float p11 = ((Wo1 >> b0) & 1u)       ? fmaxf(eA1.x * e0.z, eA1.y * e0.w) : 0.f;
            float p12 = ((We1 >> (b0 + 2)) & 1u) ? fmaxf(eA1.x * e1.x, eA1.y * e1.y) : 0.f;
            float p13 = ((Wo1 >> (b0 + 2)) & 1u) ? fmaxf(eA1.x * e1.z, eA1.y * e1.w) : 0.f;
            Sacc0 += (p00 + p01) + (p02 + p03);
            Sacc1 += (p10 + p11) + (p12 + p13);
            split2(p00, p01, AH[kk][0], AL[kk][0]);   // (r,   k0..1)
            split2(p10, p11, AH[kk][1], AL[kk][1]);   // (r+8, k0..1)
            split2(p02, p03, AH[kk][2], AL[kk][2]);   // (r,   k8..9)
            split2(p12, p13, AH[kk][3], AL[kk][3]);   // (r+8, k8..9)
        }

        if (tt < 15) { CPWAIT1(); } else { CPWAIT0(); }
        __syncthreads();   // HT(tt) staged & visible

        // ---- MMA: m16 x n64 x k64 (this warp's k-half) ----
#pragma unroll
        for (int kk = 0; kk < 4; ++kk) {
            const u32 koff = stoff + (u32)(kk * 32);
#pragma unroll
            for (int nq = 0; nq < 4; ++nq) {
                const u32 aB = aBbase + (u32)(nq * 16 * PSTRIDE) + koff;
                u32 bh[4], bl[4];
                LDSM4(bh[0], bh[1], bh[2], bh[3], aB);
                LDSM4(bl[0], bl[1], bl[2], bl[3], aB + OF_HTL);
                MMA16816(d[2 * nq],     AH[kk], bh[0], bh[2]);
                MMA16816(d[2 * nq + 1], AH[kk], bh[1], bh[3]);
                MMA16816(d[2 * nq],     AL[kk], bh[0], bh[2]);
                MMA16816(d[2 * nq + 1], AL[kk], bh[1], bh[3]);
                MMA16816(d[2 * nq],     AH[kk], bl[0], bl[2]);
                MMA16816(d[2 * nq + 1], AH[kk], bl[1], bl[3]);
            }
        }
        __syncthreads();   // all reads of stage tt done before it is rewritten
    }

    // ---- reduce warp pairs (kh=1 -> kh=0) via smem ----
    float* Sp = (float*)(smem + SM_SP);
    Sacc0 += __shfl_xor_sync(0xffffffffu, Sacc0, 1);
    Sacc0 += __shfl_xor_sync(0xffffffffu, Sacc0, 2);
    Sacc1 += __shfl_xor_sync(0xffffffffu, Sacc1, 1);
    Sacc1 += __shfl_xor_sync(0xffffffffu, Sacc1, 2);

    float4* Dred = (float4*)smem;    // reuse HT stage0 (16KB)
    if (kh == 1) {
        const int base = (mq * 32 + lane) * 8;
#pragma unroll
        for (int nb = 0; nb < 8; ++nb)
            Dred[base + nb] = make_float4(d[nb][0], d[nb][1], d[nb][2], d[nb][3]);
        if ((lane & 3) == 0) {
            Sp[rloc] = Sacc0;
            Sp[rloc + 8] = Sacc1;
        }
    }
    __syncthreads();

    if (kh == 0) {
        const int base = (mq * 32 + lane) * 8;
        const float inv0 = 1.0f / (Sacc0 + Sp[rloc]);
        const float inv1 = 1.0f / (Sacc1 + Sp[rloc + 8]);
        float* o0 = out + ((size_t)(b * NN + i0 + rloc)) * FF + tig * 2;
        float* o1 = out + ((size_t)(b * NN + i0 + rloc + 8)) * FF + tig * 2;
#pragma unroll
        for (int nb = 0; nb < 8; ++nb) {
            const float4 v = Dred[base + nb];
            float v0 = (d[nb][0] + v.x) * inv0, v1 = (d[nb][1] + v.y) * inv0;
            float v2 = (d[nb][2] + v.z) * inv1, v3 = (d[nb][3] + v.w) * inv1;
            v0 = v0 > 0.f ? v0 : expm1f(v0);
            v1 = v1 > 0.f ? v1 : expm1f(v1);
            v2 = v2 > 0.f ? v2 : expm1f(v2);
            v3 = v3 > 0.f ? v3 : expm1f(v3);
            *(float2*)(o0 + nb * 8) = make_float2(v0, v1);
            *(float2*)(o1 + nb * 8) = make_float2(v2, v3);
        }
    }
}

// ---------------------------------------------------------------------------
extern "C" void kernel_launch(void* const* d_in, const int* in_sizes, int n_in,
                              void* d_out, int out_size) {
    const float* inp = (const float*)d_in[0];
    const int*   adj = (const int*)d_in[1];
    const float* W   = (const float*)d_in[2];
    const float* a   = (const float*)d_in[3];
    float* out = (float*)d_out;

    cudaFuncSetAttribute(k_hf, cudaFuncAttributeMaxDynamicSharedMemorySize, KHF_SMEM);
    cudaFuncSetAttribute(k_attn, cudaFuncAttributeMaxDynamicSharedMemorySize, ATTN_SMEM);

    k_hf<<<128 + 256, 512, KHF_SMEM>>>(inp, W, a, adj);
    dim3 g(NN / 64, BB);
    k_attn<<<g, 256, ATTN_SMEM>>>(out);
}

// round 13
// speedup vs baseline: 1.1624x; 1.1624x over previous
#include <cuda_runtime.h>
#include <cuda_bf16.h>
#include <math.h>
#include <stdint.h>

#define BB 8
#define NN 2048
#define FF 64

typedef unsigned long long u64;
typedef unsigned int u32;

// -------------------- device scratch --------------------
// eA scaled by 2^-6 (row-uniform, cancels in softmax): (e^f1, e^{0.2 f1})*2^-6
__device__ __align__(16) float2 g_eA[BB * NN];
__device__ __align__(16) float2 g_eB[BB * NN];   // (e^f2, e^{0.2 f2}) unscaled
// H^T fp16 planes: [b][n(64)][j(2048)] as u32 pairs (2 fp16 each)
__device__ __align__(16) u32 g_hTh[BB * FF * (NN / 2)];
__device__ __align__(16) u32 g_hTl[BB * FF * (NN / 2)];
// word g, component c, bit L  <->  adj[g*128 + 4L + c]
__device__ __align__(16) uint4 g_mask[BB * NN * 16];

// -------------------- PTX helpers --------------------
#define FMA2(d, a, b, c) \
    asm("fma.rn.f32x2 %0,%1,%2,%3;" : "=l"(d) : "l"(a), "l"(b), "l"(c))
#define UNPACK2(lo, hi, s) \
    asm("mov.b64 {%0,%1},%2;" : "=f"(lo), "=f"(hi) : "l"(s))

__device__ __forceinline__ float ex2(float x) {
    float r; asm("ex2.approx.ftz.f32 %0,%1;" : "=f"(r) : "f"(x)); return r;
}
__device__ __forceinline__ u32 smem_u32(const void* p) {
    u32 a;
    asm("{.reg .u64 t; cvta.to.shared.u64 t, %1; cvt.u32.u64 %0, t;}"
        : "=r"(a) : "l"(p));
    return a;
}

#define CPASYNC16(saddr, gptr) \
    asm volatile("cp.async.ca.shared.global [%0], [%1], 16;" \
                 :: "r"(saddr), "l"(gptr) : "memory")
#define CPCOMMIT() asm volatile("cp.async.commit_group;" ::: "memory")
#define CPWAIT0()  asm volatile("cp.async.wait_group 0;" ::: "memory")
#define CPWAIT1()  asm volatile("cp.async.wait_group 1;" ::: "memory")

#define LDSM4(r0, r1, r2, r3, addr) \
    asm volatile("ldmatrix.sync.aligned.m8n8.x4.shared.b16 {%0,%1,%2,%3}, [%4];" \
                 : "=r"(r0), "=r"(r1), "=r"(r2), "=r"(r3) : "r"(addr))

#define MMAH16816(d, a, b0, b1) \
    asm volatile("mma.sync.aligned.m16n8k16.row.col.f32.f16.f16.f32 " \
                 "{%0,%1,%2,%3}, {%4,%5,%6,%7}, {%8,%9}, {%0,%1,%2,%3};" \
                 : "+f"((d)[0]), "+f"((d)[1]), "+f"((d)[2]), "+f"((d)[3]) \
                 : "r"((a)[0]), "r"((a)[1]), "r"((a)[2]), "r"((a)[3]), \
                   "r"(b0), "r"(b1))

// pack 2 floats into f16x2 (first value in low half)
#define PACKH2(d, a, b) \
    asm("cvt.rn.f16x2.f32 %0,%1,%2;" : "=r"(d) : "f"(b), "f"(a))

// fp16 two-term split of a pair (first value in low half of each word)
__device__ __forceinline__ void split2h(float a, float b, u32& hi, u32& lo) {
    asm("cvt.rn.f16x2.f32 %0,%1,%2;" : "=r"(hi) : "f"(b), "f"(a));
    float ah, bh;
    asm("{.reg .f16 x,y; mov.b32 {x,y},%2; cvt.f32.f16 %0,x; cvt.f32.f16 %1,y;}"
        : "=f"(ah), "=f"(bh) : "r"(hi));
    float ra = a - ah, rb = b - bh;
    asm("cvt.rn.f16x2.f32 %0,%1,%2;" : "=r"(lo) : "f"(rb), "f"(ra));
}

// ---------------------------------------------------------------------------
// Kernel 1: blocks [0,128): h = inp@W, exp factors, H^T fp16 hi/lo planes.
//           blocks [128,384): adj -> ballot bitmask.
// ---------------------------------------------------------------------------
#define PR2 130
#define KHF_SMEM (FF * FF * 4 + FF * PR2 * 8)

__global__ void __launch_bounds__(512) k_hf(const float* __restrict__ inp,
                                            const float* __restrict__ W,
                                            const float* __restrict__ a,
                                            const int* __restrict__ adj) {
    const int t = threadIdx.x;
    const float L2E = 1.44269504089f;

    if (blockIdx.x >= 128) {
        const int gw = (blockIdx.x - 128) * 16 + (t >> 5);
        const int lane = t & 31;
        const int4* src = (const int4*)adj + (size_t)gw * 64 * 32 + lane;
        uint4* dst = g_mask + (size_t)gw * 64;
#pragma unroll 1
        for (int r = 0; r < 8; ++r) {
            int4 v[8];
#pragma unroll
            for (int s = 0; s < 8; ++s) v[s] = src[(r * 8 + s) * 32];
#pragma unroll
            for (int s = 0; s < 8; ++s) {
                uint4 m;
                m.x = __ballot_sync(0xffffffffu, v[s].x > 0);
                m.y = __ballot_sync(0xffffffffu, v[s].y > 0);
                m.z = __ballot_sync(0xffffffffu, v[s].z > 0);
                m.w = __ballot_sync(0xffffffffu, v[s].w > 0);
                if (lane == 0) dst[r * 8 + s] = m;
            }
        }
        return;
    }

    extern __shared__ char smem[];
    float*  Ws   = (float*)smem;
    float2* IsT2 = (float2*)(smem + FF * FF * 4);

    const int row0 = blockIdx.x * 128;
    const int tx   = t & 7;
    const int ty   = t >> 3;

    ((float4*)Ws)[t]       = ((const float4*)W)[t];
    ((float4*)Ws)[t + 512] = ((const float4*)W)[t + 512];
#pragma unroll
    for (int q = 0; q < 4; ++q) {
        int idx = t + 512 * q;
        int r = idx >> 4, k4 = (idx & 15) * 4;
        float4 v = ((const float4*)(inp + (size_t)(row0 + r) * FF))[idx & 15];
        IsT2[(k4 + 0) * PR2 + r] = make_float2(v.x, v.x);
        IsT2[(k4 + 1) * PR2 + r] = make_float2(v.y, v.y);
        IsT2[(k4 + 2) * PR2 + r] = make_float2(v.z, v.z);
        IsT2[(k4 + 3) * PR2 + r] = make_float2(v.w, v.w);
    }
    __syncthreads();

    u64 acc[2][4] = {};
#pragma unroll 8
    for (int k = 0; k < FF; ++k) {
        ulonglong2 pp = *(const ulonglong2*)&IsT2[k * PR2 + ty * 2];
        u64 pd[2] = {pp.x, pp.y};
        ulonglong2 h0 = *(const ulonglong2*)&Ws[k * FF + tx * 8];
        ulonglong2 h1 = *(const ulonglong2*)&Ws[k * FF + tx * 8 + 4];
        u64 hp[4] = {h0.x, h0.y, h1.x, h1.y};
#pragma unroll
        for (int r = 0; r < 2; ++r)
#pragma unroll
            for (int c = 0; c < 4; ++c) FMA2(acc[r][c], pd[r], hp[c], acc[r][c]);
    }

    float hv[2][8];
#pragma unroll
    for (int r = 0; r < 2; ++r)
#pragma unroll
        for (int c = 0; c < 4; ++c)
            UNPACK2(hv[r][2 * c], hv[r][2 * c + 1], acc[r][c]);

    float av1[8], av2[8];
#pragma unroll
    for (int c = 0; c < 8; ++c) {
        av1[c] = __ldg(a + tx * 8 + c);
        av2[c] = __ldg(a + 64 + tx * 8 + c);
    }
#pragma unroll
    for (int r = 0; r < 2; ++r) {
        float s1 = 0.f, s2 = 0.f;
#pragma unroll
        for (int c = 0; c < 8; ++c) { s1 += hv[r][c] * av1[c]; s2 += hv[r][c] * av2[c]; }
#pragma unroll
        for (int o = 1; o < 8; o <<= 1) {
            s1 += __shfl_xor_sync(0xffffffffu, s1, o);
            s2 += __shfl_xor_sync(0xffffffffu, s2, o);
        }
        if (tx == 0) {
            const int row = row0 + ty * 2 + r;
            const float t1 = s1 * L2E, t2 = s2 * L2E;
            // eA scaled by 2^-6 to keep p in fp16 range (cancels in softmax)
            g_eA[row] = make_float2(ex2(t1 - 6.0f), ex2(0.2f * t1 - 6.0f));
            g_eB[row] = make_float2(ex2(t2), ex2(0.2f * t2));
        }
    }

    __syncthreads();
    u32* trH = (u32*)(smem + 16384);
    u32* trL = trH + 64 * 68;
#pragma unroll
    for (int c = 0; c < 8; ++c) {
        const int n = tx * 8 + c;
        u32 hi, lo;
        split2h(hv[0][c], hv[1][c], hi, lo);
        trH[n * 68 + ty] = hi;
        trL[n * 68 + ty] = lo;
    }
    __syncthreads();

    const int b     = row0 >> 11;
    const int jloc0 = row0 & 2047;
    float4* dH = (float4*)g_hTh;
    float4* dL = (float4*)g_hTl;
#pragma unroll
    for (int u = 0; u < 2; ++u) {
        const int idx = t + 512 * u;
        const int n = idx >> 4, c = idx & 15;
        const int gidx = (b * 64 + n) * 256 + (jloc0 >> 3) + c;
        dH[gidx] = *(const float4*)(trH + n * 68 + c * 4);
        dL[gidx] = *(const float4*)(trL + n * 68 + c * 4);
    }
}

// ---------------------------------------------------------------------------
// Kernel 2: P in fp16 fragment registers (single plane); H fp16 hi/lo.
// 2 MMA terms: Ph@Hh + Ph@Hl. 256 CTAs x 256 threads, 2 CTAs/SM.
// Mask layout (interleaved ballot) consumed as validated in R12.
// ---------------------------------------------------------------------------
#define PSTRIDE 272
#define HT_STG  34816            // per stage: HTH(0), HTL(17408)
#define OF_HTL  17408
#define SM_MSK  69632
#define SM_EB   86016
#define SM_SP   102400
#define ATTN_SMEM 102912

__global__ void __launch_bounds__(256, 2) k_attn(float* __restrict__ out) {
    extern __shared__ char smem[];
    const u32 sb = smem_u32(smem);
    const int t = threadIdx.x;
    const int w = t >> 5, lane = t & 31;
    const int i0 = blockIdx.x * 64;
    const int b  = blockIdx.y;
    const int mq = w & 3;            // m16 block
    const int kh = w >> 2;           // k-half

    uint4*  msk_s = (uint4*)(smem + SM_MSK);
    float4* ebs4  = (float4*)(smem + SM_EB);

    const float4* hsH = (const float4*)g_hTh + (size_t)b * 64 * 256;
    const float4* hsL = (const float4*)g_hTl + (size_t)b * 64 * 256;
    const int stg_n = t >> 4, stg_c = t & 15;

    // ---- prologue: masks + eB pairs + HT(0) ----
    {
        const uint4* gm = g_mask + (size_t)(b * NN + i0) * 16;
#pragma unroll
        for (int u = 0; u < 4; ++u) msk_s[t + 256 * u] = gm[t + 256 * u];
        const float4* ebg = (const float4*)(g_eB + (size_t)b * NN);
#pragma unroll
        for (int u = 0; u < 4; ++u) ebs4[t + 256 * u] = ebg[t + 256 * u];
#pragma unroll
        for (int u = 0; u < 4; ++u) {
            const int n = stg_n + 16 * u;
            const int g = (n << 8) + stg_c;
            const u32 so = (u32)(n * PSTRIDE + stg_c * 16);
            CPASYNC16(sb + so, hsH + g);
            CPASYNC16(sb + OF_HTL + so, hsL + g);
        }
        CPCOMMIT();
    }

    const int tig  = lane & 3;
    const int rloc = mq * 16 + (lane >> 2);
    const float2 eA0 = __ldg(&g_eA[b * NN + i0 + rloc]);
    const float2 eA1 = __ldg(&g_eA[b * NN + i0 + rloc + 8]);
    float Sacc0 = 0.f, Sacc1 = 0.f;

    const u32 rowsel = (u32)(lane & 15);
    const u32 colsel = (u32)((lane >> 4) * 16);
    const u32 aBbase = sb + rowsel * PSTRIDE + colsel + (u32)kh * 128;
    const u32 bbase  = (u32)(kh * 16 + (tig >> 1));

    float d[8][4] = {};

    __syncthreads();   // masks/eB visible

    for (int tt = 0; tt < 16; ++tt) {
        const u32 stoff = (u32)((tt & 1) * HT_STG);

        if (tt < 15) {
            const u32 stoffN = (u32)(((tt + 1) & 1) * HT_STG);
#pragma unroll
            for (int u = 0; u < 4; ++u) {
                const int n = stg_n + 16 * u;
                const int g = (n << 8) + ((tt + 1) << 4) + stg_c;
                const u32 so = (u32)(n * PSTRIDE + stg_c * 16);
                CPASYNC16(sb + stoffN + so, hsH + g);
                CPASYNC16(sb + stoffN + OF_HTL + so, hsL + g);
            }
            CPCOMMIT();
        }

        // ---- scores -> single fp16 A fragments (registers only) ----
        const uint4 mr0 = msk_s[rloc * 16 + tt];
        const uint4 mr1 = msk_s[(rloc + 8) * 16 + tt];
        const u32 We0 = (tig & 1) ? mr0.z : mr0.x;
        const u32 Wo0 = (tig & 1) ? mr0.w : mr0.y;
        const u32 We1 = (tig & 1) ? mr1.z : mr1.x;
        const u32 Wo1 = (tig & 1) ? mr1.w : mr1.y;

        u32 AH[4][4];
#pragma unroll
        for (int kk = 0; kk < 4; ++kk) {
            const int idx = tt * 64 + kh * 32 + kk * 8 + tig;
            const float4 e0 = ebs4[idx];
            const float4 e1 = ebs4[idx + 4];
            const u32 b0 = bbase + (u32)(kk * 4);

            float p00 = ((We0 >> b0) & 1u)       ? fmaxf(eA0.x * e0.x, eA0.y * e0.y) : 0.f;
            float p01 = ((Wo0 >> b0) & 1u)       ? fmaxf(eA0.x * e0.z, eA0.y * e0.w) : 0.f;
            float p02 = ((We0 >> (b0 + 2)) & 1u) ? fmaxf(eA0.x * e1.x, eA0.y * e1.y) : 0.f;
            float p03 = ((Wo0 >> (b0 + 2)) & 1u) ? fmaxf(eA0.x * e1.z, eA0.y * e1.w) : 0.f;
            float p10 = ((We1 >> b0) & 1u)       ? fmaxf(eA1.x * e0.x, eA1.y * e0.y) : 0.f;
            float p11 = ((Wo1 >> b0) & 1u)       ? fmaxf(eA1.x * e0.z, eA1.y * e0.w) : 0.f;
            float p12 = ((We1 >> (b0 + 2)) & 1u) ? fmaxf(eA1.x * e1.x, eA1.y * e1.y) : 0.f;
            float p13 = ((Wo1 >> (b0 + 2)) & 1u) ? fmaxf(eA1.x * e1.z, eA1.y * e1.w) : 0.f;
            Sacc0 += (p00 + p01) + (p02 + p03);
            Sacc1 += (p10 + p11) + (p12 + p13);
            PACKH2(AH[kk][0], p00, p01);   // (r,   k0..1)
            PACKH2(AH[kk][1], p10, p11);   // (r+8, k0..1)
            PACKH2(AH[kk][2], p02, p03);   // (r,   k8..9)
            PACKH2(AH[kk][3], p12, p13);   // (r+8, k8..9)
        }

        if (tt < 15) { CPWAIT1(); } else { CPWAIT0(); }
        __syncthreads();   // HT(tt) staged & visible

        // ---- MMA: m16 x n64 x k64, 2 terms (Hh + Hl) ----
#pragma unroll
        for (int kk = 0; kk < 4; ++kk) {
            const u32 koff = stoff + (u32)(kk * 32);
#pragma unroll
            for (int nq = 0; nq < 4; ++nq) {
                const u32 aB = aBbase + (u32)(nq * 16 * PSTRIDE) + koff;
                u32 bh[4], bl[4];
                LDSM4(bh[0], bh[1], bh[2], bh[3], aB);
                LDSM4(bl[0], bl[1], bl[2], bl[3], aB + OF_HTL);
                MMAH16816(d[2 * nq],     AH[kk], bh[0], bh[2]);
                MMAH16816(d[2 * nq + 1], AH[kk], bh[1], bh[3]);
                MMAH16816(d[2 * nq],     AH[kk], bl[0], bl[2]);
                MMAH16816(d[2 * nq + 1], AH[kk], bl[1], bl[3]);
            }
        }
        __syncthreads();   // all reads of stage tt done before it is rewritten
    }

    // ---- reduce warp pairs (kh=1 -> kh=0) via smem ----
    float* Sp = (float*)(smem + SM_SP);
    Sacc0 += __shfl_xor_sync(0xffffffffu, Sacc0, 1);
    Sacc0 += __shfl_xor_sync(0xffffffffu, Sacc0, 2);
    Sacc1 += __shfl_xor_sync(0xffffffffu, Sacc1, 1);
    Sacc1 += __shfl_xor_sync(0xffffffffu, Sacc1, 2);

    float4* Dred = (float4*)smem;    // reuse HT stage0 (16KB)
    if (kh == 1) {
        const int base = (mq * 32 + lane) * 8;
#pragma unroll
        for (int nb = 0; nb < 8; ++nb)
            Dred[base + nb] = make_float4(d[nb][0], d[nb][1], d[nb][2], d[nb][3]);
        if ((lane & 3) == 0) {
            Sp[rloc] = Sacc0;
            Sp[rloc + 8] = Sacc1;
        }
    }
    __syncthreads();

    if (kh == 0) {
        const int base = (mq * 32 + lane) * 8;
        const float inv0 = 1.0f / (Sacc0 + Sp[rloc]);
        const float inv1 = 1.0f / (Sacc1 + Sp[rloc + 8]);
        float* o0 = out + ((size_t)(b * NN + i0 + rloc)) * FF + tig * 2;
        float* o1 = out + ((size_t)(b * NN + i0 + rloc + 8)) * FF + tig * 2;
#pragma unroll
        for (int nb = 0; nb < 8; ++nb) {
            const float4 v = Dred[base + nb];
            float v0 = (d[nb][0] + v.x) * inv0, v1 = (d[nb][1] + v.y) * inv0;
            float v2 = (d[nb][2] + v.z) * inv1, v3 = (d[nb][3] + v.w) * inv1;
            v0 = v0 > 0.f ? v0 : expm1f(v0);
            v1 = v1 > 0.f ? v1 : expm1f(v1);
            v2 = v2 > 0.f ? v2 : expm1f(v2);
            v3 = v3 > 0.f ? v3 : expm1f(v3);
            *(float2*)(o0 + nb * 8) = make_float2(v0, v1);
            *(float2*)(o1 + nb * 8) = make_float2(v2, v3);
        }
    }
}

// ---------------------------------------------------------------------------
extern "C" void kernel_launch(void* const* d_in, const int* in_sizes, int n_in,
                              void* d_out, int out_size) {
    const float* inp = (const float*)d_in[0];
    const int*   adj = (const int*)d_in[1];
    const float* W   = (const float*)d_in[2];
    const float* a   = (const float*)d_in[3];
    float* out = (float*)d_out;

    cudaFuncSetAttribute(k_hf, cudaFuncAttributeMaxDynamicSharedMemorySize, KHF_SMEM);
    cudaFuncSetAttribute(k_attn, cudaFuncAttributeMaxDynamicSharedMemorySize, ATTN_SMEM);

    k_hf<<<128 + 256, 512, KHF_SMEM>>>(inp, W, a, adj);
    dim3 g(NN / 64, BB);
    k_attn<<<g, 256, ATTN_SMEM>>>(out);
}

// round 15
// speedup vs baseline: 1.4706x; 1.2652x over previous
#include <cuda_runtime.h>
#include <cuda_bf16.h>
#include <math.h>
#include <stdint.h>

#define BB 8
#define NN 2048
#define FF 64

typedef unsigned long long u64;
typedef unsigned int u32;

// -------------------- device scratch --------------------
// eA scaled by 2^-6 (row-uniform, cancels in softmax): (e^f1, e^{0.2 f1})*2^-6
__device__ __align__(16) float2 g_eA[BB * NN];
__device__ __align__(16) float2 g_eB[BB * NN];   // (e^f2, e^{0.2 f2})
// H^T fp16 plane: [b][n(64)][j(2048)] as u32 pairs (2 fp16 each)
__device__ __align__(16) u32 g_hTh[BB * FF * (NN / 2)];
// word g, component c, bit L  <->  adj[g*128 + 4L + c]
__device__ __align__(16) uint4 g_mask[BB * NN * 16];

// -------------------- PTX helpers --------------------
#define FMA2(d, a, b, c) \
    asm("fma.rn.f32x2 %0,%1,%2,%3;" : "=l"(d) : "l"(a), "l"(b), "l"(c))
#define MUL2(d, a, b) \
    asm("mul.rn.f32x2 %0,%1,%2;" : "=l"(d) : "l"(a), "l"(b))
#define UNPACK2(lo, hi, s) \
    asm("mov.b64 {%0,%1},%2;" : "=f"(lo), "=f"(hi) : "l"(s))
#define PACKF2(d, lo, hi) \
    asm("mov.b64 %0,{%1,%2};" : "=l"(d) : "f"(lo), "f"(hi))

__device__ __forceinline__ float ex2(float x) {
    float r; asm("ex2.approx.ftz.f32 %0,%1;" : "=f"(r) : "f"(x)); return r;
}
__device__ __forceinline__ u32 smem_u32(const void* p) {
    u32 a;
    asm("{.reg .u64 t; cvta.to.shared.u64 t, %1; cvt.u32.u64 %0, t;}"
        : "=r"(a) : "l"(p));
    return a;
}

#define CPASYNC16(saddr, gptr) \
    asm volatile("cp.async.ca.shared.global [%0], [%1], 16;" \
                 :: "r"(saddr), "l"(gptr) : "memory")
#define CPCOMMIT() asm volatile("cp.async.commit_group;" ::: "memory")
#define CPWAIT0()  asm volatile("cp.async.wait_group 0;" ::: "memory")
#define CPWAIT1()  asm volatile("cp.async.wait_group 1;" ::: "memory")

#define LDSM4(r0, r1, r2, r3, addr) \
    asm volatile("ldmatrix.sync.aligned.m8n8.x4.shared.b16 {%0,%1,%2,%3}, [%4];" \
                 : "=r"(r0), "=r"(r1), "=r"(r2), "=r"(r3) : "r"(addr))

#define MMAH16816(d, a, b0, b1) \
    asm volatile("mma.sync.aligned.m16n8k16.row.col.f32.f16.f16.f32 " \
                 "{%0,%1,%2,%3}, {%4,%5,%6,%7}, {%8,%9}, {%0,%1,%2,%3};" \
                 : "+f"((d)[0]), "+f"((d)[1]), "+f"((d)[2]), "+f"((d)[3]) \
                 : "r"((a)[0]), "r"((a)[1]), "r"((a)[2]), "r"((a)[3]), \
                   "r"(b0), "r"(b1))

// pack 2 floats into f16x2 (first value in low half)
#define PACKH2(d, a, b) \
    asm("cvt.rn.f16x2.f32 %0,%1,%2;" : "=r"(d) : "f"(b), "f"(a))

// ---------------------------------------------------------------------------
// Kernel 1: blocks [0,128): h = inp@W, exp factors, H^T fp16 plane.
//           blocks [128,384): adj -> ballot bitmask.
// ---------------------------------------------------------------------------
#define PR2 130
#define KHF_SMEM (FF * FF * 4 + FF * PR2 * 8)

__global__ void __launch_bounds__(512) k_hf(const float* __restrict__ inp,
                                            const float* __restrict__ W,
                                            const float* __restrict__ a,
                                            const int* __restrict__ adj) {
    const int t = threadIdx.x;
    const float L2E = 1.44269504089f;

    if (blockIdx.x >= 128) {
        const int gw = (blockIdx.x - 128) * 16 + (t >> 5);
        const int lane = t & 31;
        const int4* src = (const int4*)adj + (size_t)gw * 64 * 32 + lane;
        uint4* dst = g_mask + (size_t)gw * 64;
#pragma unroll 1
        for (int r = 0; r < 8; ++r) {
            int4 v[8];
#pragma unroll
            for (int s = 0; s < 8; ++s) v[s] = src[(r * 8 + s) * 32];
#pragma unroll
            for (int s = 0; s < 8; ++s) {
                uint4 m;
                m.x = __ballot_sync(0xffffffffu, v[s].x > 0);
                m.y = __ballot_sync(0xffffffffu, v[s].y > 0);
                m.z = __ballot_sync(0xffffffffu, v[s].z > 0);
                m.w = __ballot_sync(0xffffffffu, v[s].w > 0);
                if (lane == 0) dst[r * 8 + s] = m;
            }
        }
        return;
    }

    extern __shared__ char smem[];
    float*  Ws   = (float*)smem;
    float2* IsT2 = (float2*)(smem + FF * FF * 4);

    const int row0 = blockIdx.x * 128;
    const int tx   = t & 7;
    const int ty   = t >> 3;

    ((float4*)Ws)[t]       = ((const float4*)W)[t];
    ((float4*)Ws)[t + 512] = ((const float4*)W)[t + 512];
#pragma unroll
    for (int q = 0; q < 4; ++q) {
        int idx = t + 512 * q;
        int r = idx >> 4, k4 = (idx & 15) * 4;
        float4 v = ((const float4*)(inp + (size_t)(row0 + r) * FF))[idx & 15];
        IsT2[(k4 + 0) * PR2 + r] = make_float2(v.x, v.x);
        IsT2[(k4 + 1) * PR2 + r] = make_float2(v.y, v.y);
        IsT2[(k4 + 2) * PR2 + r] = make_float2(v.z, v.z);
        IsT2[(k4 + 3) * PR2 + r] = make_float2(v.w, v.w);
    }
    __syncthreads();

    u64 acc[2][4] = {};
#pragma unroll 8
    for (int k = 0; k < FF; ++k) {
        ulonglong2 pp = *(const ulonglong2*)&IsT2[k * PR2 + ty * 2];
        u64 pd[2] = {pp.x, pp.y};
        ulonglong2 h0 = *(const ulonglong2*)&Ws[k * FF + tx * 8];
        ulonglong2 h1 = *(const ulonglong2*)&Ws[k * FF + tx * 8 + 4];
        u64 hp[4] = {h0.x, h0.y, h1.x, h1.y};
#pragma unroll
        for (int r = 0; r < 2; ++r)
#pragma unroll
            for (int c = 0; c < 4; ++c) FMA2(acc[r][c], pd[r], hp[c], acc[r][c]);
    }

    float hv[2][8];
#pragma unroll
    for (int r = 0; r < 2; ++r)
#pragma unroll
        for (int c = 0; c < 4; ++c)
            UNPACK2(hv[r][2 * c], hv[r][2 * c + 1], acc[r][c]);

    float av1[8], av2[8];
#pragma unroll
    for (int c = 0; c < 8; ++c) {
        av1[c] = __ldg(a + tx * 8 + c);
        av2[c] = __ldg(a + 64 + tx * 8 + c);
    }
#pragma unroll
    for (int r = 0; r < 2; ++r) {
        float s1 = 0.f, s2 = 0.f;
#pragma unroll
        for (int c = 0; c < 8; ++c) { s1 += hv[r][c] * av1[c]; s2 += hv[r][c] * av2[c]; }
#pragma unroll
        for (int o = 1; o < 8; o <<= 1) {
            s1 += __shfl_xor_sync(0xffffffffu, s1, o);
            s2 += __shfl_xor_sync(0xffffffffu, s2, o);
        }
        if (tx == 0) {
            const int row = row0 + ty * 2 + r;
            const float t1 = s1 * L2E, t2 = s2 * L2E;
            g_eA[row] = make_float2(ex2(t1 - 6.0f), ex2(0.2f * t1 - 6.0f));
            g_eB[row] = make_float2(ex2(t2), ex2(0.2f * t2));
        }
    }

    __syncthreads();
    u32* trH = (u32*)(smem + 16384);
#pragma unroll
    for (int c = 0; c < 8; ++c) {
        const int n = tx * 8 + c;
        u32 hi;
        PACKH2(hi, hv[0][c], hv[1][c]);
        trH[n * 68 + ty] = hi;
    }
    __syncthreads();

    const int b     = row0 >> 11;
    const int jloc0 = row0 & 2047;
    float4* dH = (float4*)g_hTh;
    {
        const int n0 = t >> 4, c0 = t & 15;
        dH[(b * 64 + n0) * 256 + (jloc0 >> 3) + c0] =
            *(const float4*)(trH + n0 * 68 + c0 * 4);
        const int idx1 = t + 512;
        const int n1 = idx1 >> 4, c1 = idx1 & 15;
        dH[(b * 64 + n1) * 256 + (jloc0 >> 3) + c1] =
            *(const float4*)(trH + n1 * 68 + c1 * 4);
    }
}

// ---------------------------------------------------------------------------
// Kernel 2: P in fp16 fragment registers; single MMA term Ph@Hh.
// 256 CTAs x 256 threads, 3 CTAs/SM (67.8KB smem). Double-buffered HT.
// smem layout: [HT0 0:17408][HT1 17408:34816][MSK 34816:51200]
//              [EB 51200:67584][SP 67584:67840]
// ---------------------------------------------------------------------------
#define PSTRIDE 272
#define HT_STG  17408
#define SM_MSK  34816
#define SM_EB   51200
#define SM_SP   67584
#define ATTN_SMEM 67840

__global__ void __launch_bounds__(256, 3) k_attn(float* __restrict__ out) {
    extern __shared__ char smem[];
    const u32 sb = smem_u32(smem);
    const int t = threadIdx.x;
    const int w = t >> 5, lane = t & 31;
    const int i0 = blockIdx.x * 64;
    const int b  = blockIdx.y;
    const int mq = w & 3;            // m16 block
    const int kh = w >> 2;           // k-half

    uint4* msk_s = (uint4*)(smem + SM_MSK);
    const ulonglong2* ebs = (const ulonglong2*)(smem + SM_EB); // ((B,b),(B,b))

    const float4* hsH = (const float4*)g_hTh + (size_t)b * 64 * 256;
    const int stg_n = t >> 4, stg_c = t & 15;

    // ---- prologue: masks + eB pairs + HT(0) ----
    {
        const uint4* gm = g_mask + (size_t)(b * NN + i0) * 16;
#pragma unroll
        for (int u = 0; u < 4; ++u) msk_s[t + 256 * u] = gm[t + 256 * u];
        const float4* ebg = (const float4*)(g_eB + (size_t)b * NN);
#pragma unroll
        for (int u = 0; u < 4; ++u)
            ((float4*)(smem + SM_EB))[t + 256 * u] = ebg[t + 256 * u];
        const int n = stg_n, g = (n << 8) + stg_c;
        const u32 so = (u32)(n * PSTRIDE + stg_c * 16);
        CPASYNC16(sb + so, hsH + g);
        CPASYNC16(sb + so + 16 * PSTRIDE, hsH + g + (16 << 8));
        CPASYNC16(sb + so + 32 * PSTRIDE, hsH + g + (32 << 8));
        CPASYNC16(sb + so + 48 * PSTRIDE, hsH + g + (48 << 8));
        CPCOMMIT();
    }

    const int tig  = lane & 3;
    const int rloc = mq * 16 + (lane >> 2);
    u64 eA0d, eA1d;
    {
        const float2 e0 = __ldg(&g_eA[b * NN + i0 + rloc]);
        const float2 e1 = __ldg(&g_eA[b * NN + i0 + rloc + 8]);
        PACKF2(eA0d, e0.x, e0.y);
        PACKF2(eA1d, e1.x, e1.y);
    }
    float Sacc0 = 0.f, Sacc1 = 0.f;

    const u32 rowsel = (u32)(lane & 15);
    const u32 colsel = (u32)((lane >> 4) * 16);
    const u32 aBbase = sb + rowsel * PSTRIDE + colsel + (u32)kh * 128;
    const u32 bbase  = (u32)(kh * 16 + (tig >> 1));

    float d[8][4] = {};

    __syncthreads();   // masks/eB visible

    for (int tt = 0; tt < 16; ++tt) {
        const u32 stoff = (u32)((tt & 1) * HT_STG);

        if (tt < 15) {
            const u32 stoffN = (u32)(((tt + 1) & 1) * HT_STG);
            const int n = stg_n, g = (n << 8) + ((tt + 1) << 4) + stg_c;
            const u32 so = stoffN + (u32)(n * PSTRIDE + stg_c * 16);
            CPASYNC16(sb + so, hsH + g);
            CPASYNC16(sb + so + 16 * PSTRIDE, hsH + g + (16 << 8));
            CPASYNC16(sb + so + 32 * PSTRIDE, hsH + g + (32 << 8));
            CPASYNC16(sb + so + 48 * PSTRIDE, hsH + g + (48 << 8));
            CPCOMMIT();
        }

        // ---- scores -> fp16 A fragments (registers only, f32x2 muls) ----
        const uint4 mr0 = msk_s[rloc * 16 + tt];
        const uint4 mr1 = msk_s[(rloc + 8) * 16 + tt];
        const u32 We0 = (tig & 1) ? mr0.z : mr0.x;
        const u32 Wo0 = (tig & 1) ? mr0.w : mr0.y;
        const u32 We1 = (tig & 1) ? mr1.z : mr1.x;
        const u32 Wo1 = (tig & 1) ? mr1.w : mr1.y;

        u32 AH[4][4];
#pragma unroll
        for (int kk = 0; kk < 4; ++kk) {
            const int idx = tt * 64 + kh * 32 + kk * 8 + tig;
            const ulonglong2 e0 = ebs[idx];        // (B,b) j | (B,b) j+1
            const ulonglong2 e1 = ebs[idx + 4];    // (B,b) j+8 | (B,b) j+9
            const u32 b0 = bbase + (u32)(kk * 4);

            u64 m00, m01, m02, m03, m10, m11, m12, m13;
            MUL2(m00, eA0d, e0.x); MUL2(m01, eA0d, e0.y);
            MUL2(m02, eA0d, e1.x); MUL2(m03, eA0d, e1.y);
            MUL2(m10, eA1d, e0.x); MUL2(m11, eA1d, e0.y);
            MUL2(m12, eA1d, e1.x); MUL2(m13, eA1d, e1.y);

            float x, y, p00, p01, p02, p03, p10, p11, p12, p13;
            UNPACK2(x, y, m00); p00 = ((We0 >> b0) & 1u)       ? fmaxf(x, y) : 0.f;
            UNPACK2(x, y, m01); p01 = ((Wo0 >> b0) & 1u)       ? fmaxf(x, y) : 0.f;
            UNPACK2(x, y, m02); p02 = ((We0 >> (b0 + 2)) & 1u) ? fmaxf(x, y) : 0.f;
            UNPACK2(x, y, m03); p03 = ((Wo0 >> (b0 + 2)) & 1u) ? fmaxf(x, y) : 0.f;
            UNPACK2(x, y, m10); p10 = ((We1 >> b0) & 1u)       ? fmaxf(x, y) : 0.f;
            UNPACK2(x, y, m11); p11 = ((Wo1 >> b0) & 1u)       ? fmaxf(x, y) : 0.f;
            UNPACK2(x, y, m12); p12 = ((We1 >> (b0 + 2)) & 1u) ? fmaxf(x, y) : 0.f;
            UNPACK2(x, y, m13); p13 = ((Wo1 >> (b0 + 2)) & 1u) ? fmaxf(x, y) : 0.f;

            Sacc0 += (p00 + p01) + (p02 + p03);
            Sacc1 += (p10 + p11) + (p12 + p13);
            PACKH2(AH[kk][0], p00, p01);   // (r,   k0..1)
            PACKH2(AH[kk][1], p10, p11);   // (r+8, k0..1)
            PACKH2(AH[kk][2], p02, p03);   // (r,   k8..9)
            PACKH2(AH[kk][3], p12, p13);   // (r+8, k8..9)
        }

        if (tt < 15) { CPWAIT1(); } else { CPWAIT0(); }
        __syncthreads();   // HT(tt) staged & visible

        // ---- MMA: m16 x n64 x k64, single term ----
#pragma unroll
        for (int kk = 0; kk < 4; ++kk) {
            const u32 koff = stoff + (u32)(kk * 32);
#pragma unroll
            for (int nq = 0; nq < 4; ++nq) {
                const u32 aB = aBbase + (u32)(nq * 16 * PSTRIDE) + koff;
                u32 bh[4];
                LDSM4(bh[0], bh[1], bh[2], bh[3], aB);
                MMAH16816(d[2 * nq],     AH[kk], bh[0], bh[2]);
                MMAH16816(d[2 * nq + 1], AH[kk], bh[1], bh[3]);
            }
        }
        __syncthreads();   // all reads of stage tt done before it is rewritten
    }

    // ---- reduce warp pairs (kh=1 -> kh=0) via smem ----
    float* Sp = (float*)(smem + SM_SP);
    Sacc0 += __shfl_xor_sync(0xffffffffu, Sacc0, 1);
    Sacc0 += __shfl_xor_sync(0xffffffffu, Sacc0, 2);
    Sacc1 += __shfl_xor_sync(0xffffffffu, Sacc1, 1);
    Sacc1 += __shfl_xor_sync(0xffffffffu, Sacc1, 2);

    float4* Dred = (float4*)smem;    // reuse HT stage0 (16KB)
    if (kh == 1) {
        const int base = (mq * 32 + lane) * 8;
#pragma unroll
        for (int nb = 0; nb < 8; ++nb)
            Dred[base + nb] = make_float4(d[nb][0], d[nb][1], d[nb][2], d[nb][3]);
        if ((lane & 3) == 0) {
            Sp[rloc] = Sacc0;
            Sp[rloc + 8] = Sacc1;
        }
    }
    __syncthreads();

    if (kh == 0) {
        const int base = (mq * 32 + lane) * 8;
        const float inv0 = 1.0f / (Sacc0 + Sp[rloc]);
        const float inv1 = 1.0f / (Sacc1 + Sp[rloc + 8]);
        float* o0 = out + ((size_t)(b * NN + i0 + rloc)) * FF + tig * 2;
        float* o1 = out + ((size_t)(b * NN + i0 + rloc + 8)) * FF + tig * 2;
#pragma unroll
        for (int nb = 0; nb < 8; ++nb) {
            const float4 v = Dred[base + nb];
            float v0 = (d[nb][0] + v.x) * inv0, v1 = (d[nb][1] + v.y) * inv0;
            float v2 = (d[nb][2] + v.z) * inv1, v3 = (d[nb][3] + v.w) * inv1;
            v0 = v0 > 0.f ? v0 : expm1f(v0);
            v1 = v1 > 0.f ? v1 : expm1f(v1);
            v2 = v2 > 0.f ? v2 : expm1f(v2);
            v3 = v3 > 0.f ? v3 : expm1f(v3);
            *(float2*)(o0 + nb * 8) = make_float2(v0, v1);
            *(float2*)(o1 + nb * 8) = make_float2(v2, v3);
        }
    }
}

// ---------------------------------------------------------------------------
extern "C" void kernel_launch(void* const* d_in, const int* in_sizes, int n_in,
                              void* d_out, int out_size) {
    const float* inp = (const float*)d_in[0];
    const int*   adj = (const int*)d_in[1];
    const float* W   = (const float*)d_in[2];
    const float* a   = (const float*)d_in[3];
    float* out = (float*)d_out;

    cudaFuncSetAttribute(k_hf, cudaFuncAttributeMaxDynamicSharedMemorySize, KHF_SMEM);
    cudaFuncSetAttribute(k_attn, cudaFuncAttributeMaxDynamicSharedMemorySize, ATTN_SMEM);

    k_hf<<<128 + 256, 512, KHF_SMEM>>>(inp, W, a, adj);
    dim3 g(NN / 64, BB);
    k_attn<<<g, 256, ATTN_SMEM>>>(out);
}